// round 10
// baseline (speedup 1.0000x reference)
#include <cuda_runtime.h>
#include <cuda_fp16.h>
#include <cstdint>

// ---------------- problem constants ----------------
#define NT    8
#define RK    48
#define DIM   768
#define BATCH 32
#define CIN   256
#define COUT  256
#define HH    56
#define WW    56
#define HW    3136
#define KTOT  2304            // Cin*9, reordered as tap*256+ci
#define WELEM (COUT*KTOT)     // 589824
#define SCALING 2.0f
#define PWH   64              // padded row width in halves (128B rows)
#define PH    58
#define PPLANE (PH*PWH)       // 3712

// ---------------- scratch (device globals) ----------------
__device__ float  g_stack[NT * DIM * DIM];                 // [t][f], f = o*2304+ci*9+tap
__device__ __half g_agg[(long)BATCH * WELEM];              // [b][o][tap*256+ci], fp16
__device__ __half g_xpad[3L * BATCH * CIN * PPLANE];       // [kw][b][ci][58][64], fp16

__device__ __forceinline__ uint32_t smem_u32(const void* p) {
    uint32_t a;
    asm("{ .reg .u64 t; cvta.to.shared.u64 t, %1; cvt.u32.u64 %0, t; }" : "=r"(a) : "l"(p));
    return a;
}
__device__ __forceinline__ void cp16(uint32_t dst, const void* src) {
    asm volatile("cp.async.cg.shared.global [%0], [%1], 16;" :: "r"(dst), "l"(src));
}
__device__ __forceinline__ void ldsmA(uint32_t* r, uint32_t addr) {
    asm volatile("ldmatrix.sync.aligned.m8n8.x4.shared.b16 {%0,%1,%2,%3}, [%4];"
                 : "=r"(r[0]), "=r"(r[1]), "=r"(r[2]), "=r"(r[3]) : "r"(addr));
}
__device__ __forceinline__ void ldsmBT(uint32_t* r, uint32_t addr) {
    asm volatile("ldmatrix.sync.aligned.m8n8.x2.trans.shared.b16 {%0,%1}, [%2];"
                 : "=r"(r[0]), "=r"(r[1]) : "r"(addr));
}
// fp16-accumulate HMMA: D,C are 2x f16x2 regs
__device__ __forceinline__ void hmma16(uint32_t* d, const uint32_t* a, const uint32_t* b) {
    asm volatile(
        "mma.sync.aligned.m16n8k16.row.col.f16.f16.f16.f16 "
        "{%0,%1}, {%2,%3,%4,%5}, {%6,%7}, {%0,%1};"
        : "+r"(d[0]), "+r"(d[1])
        : "r"(a[0]), "r"(a[1]), "r"(a[2]), "r"(a[3]), "r"(b[0]), "r"(b[1]));
}

// ---------------------------------------------------------------------------
// Kernel P (R5 version — measured fastest): 3 kw-shifted zero-padded fp16
// copies of x, 16B stores. copy[kw][ci][y'][xx'] = x[ci][y'-1][xx'+kw-1]
// ---------------------------------------------------------------------------
__global__ void pad_kernel(const float* __restrict__ x) {
    int plane = blockIdx.x;                 // b*256+ci
    const float* src = x + (long)plane * HW;
#pragma unroll
    for (int kw = 0; kw < 3; kw++) {
        __half* dst = g_xpad + ((long)kw * BATCH * CIN + plane) * PPLANE;
        for (int i8 = threadIdx.x; i8 < PPLANE / 8; i8 += 256) {
            int y   = i8 >> 3;
            int xs0 = (i8 & 7) * 8;
            __half2 h[4];
#pragma unroll
            for (int p = 0; p < 4; p++) {
                float v0 = 0.f, v1 = 0.f;
                if (y >= 1 && y <= HH) {
                    const float* row = src + (y - 1) * WW;
                    int xc = xs0 + p * 2 + kw - 1;
                    if (xc >= 0 && xc < WW) v0 = row[xc];
                    if (xc + 1 >= 0 && xc + 1 < WW) v1 = row[xc + 1];
                }
                h[p] = __floats2half2_rn(v0, v1);
            }
            *(float4*)(dst + i8 * 8) = *(float4*)h;
        }
    }
}

// ---------------------------------------------------------------------------
// Kernel A: stack[t] = lora_B[t] (768x48) @ lora_A[t] (48x768)
// ---------------------------------------------------------------------------
__global__ void synth_stack_kernel(const float* __restrict__ lora_A,
                                   const float* __restrict__ lora_B) {
    int t    = blockIdx.z;
    int row0 = blockIdx.y * 32;
    int col0 = blockIdx.x * 128;
    __shared__ float Bs[32][RK + 1];
    __shared__ float As[RK][128];
    int tid = threadIdx.x;

    for (int i = tid; i < 32 * RK; i += 256) {
        int r = i / RK, k = i % RK;
        Bs[r][k] = lora_B[((long)t * DIM + row0 + r) * RK + k];
    }
    for (int i = tid; i < RK * 32; i += 256) {
        int k = i / 32, c4 = i % 32;
        *(float4*)&As[k][c4 * 4] =
            *(const float4*)(lora_A + ((long)t * RK + k) * DIM + col0 + c4 * 4);
    }
    __syncthreads();

    int r  = tid >> 3;
    int c0 = (tid & 7) * 16;
    float acc[16];
#pragma unroll
    for (int j = 0; j < 16; j++) acc[j] = 0.f;
#pragma unroll
    for (int k = 0; k < RK; k++) {
        float bv = Bs[r][k];
#pragma unroll
        for (int j = 0; j < 16; j++) acc[j] += bv * As[k][c0 + j];
    }
    float* dst = &g_stack[((long)t * DIM + row0 + r) * DIM + col0 + c0];
#pragma unroll
    for (int j4 = 0; j4 < 4; j4++)
        *(float4*)(dst + j4 * 4) = make_float4(acc[j4*4], acc[j4*4+1], acc[j4*4+2], acc[j4*4+3]);
}

// ---------------------------------------------------------------------------
// Kernel B (R5 v2, measured-best): thread handles 2 consecutive reordered
// indices, half2 stores. g = o*2304 + tap*256 + ci, f = o*2304 + ci*9 + tap.
// ---------------------------------------------------------------------------
__global__ void build_agg_kernel(const float* __restrict__ alphas,
                                 const float* __restrict__ conv_w) {
    __shared__ float sal[BATCH * NT];
    int tid = threadIdx.x;
    sal[tid] = alphas[tid];
    __syncthreads();

    long g0 = ((long)blockIdx.x * 256 + tid) * 2;
    int o   = (int)(g0 / KTOT);
    int r2  = (int)(g0 % KTOT);
    int tap = r2 >> 8;
    int ci  = r2 & 255;
    long f0 = (long)o * KTOT + ci * 9 + tap;
    long f1 = f0 + 9;

    float s0[NT], s1[NT];
#pragma unroll
    for (int t = 0; t < NT; t++) {
        s0[t] = g_stack[(long)t * WELEM + f0];
        s1[t] = g_stack[(long)t * WELEM + f1];
    }
    float w0 = conv_w[f0], w1 = conv_w[f1];

#pragma unroll 4
    for (int b = 0; b < BATCH; b++) {
        float a0 = w0, a1 = w1;
#pragma unroll
        for (int t = 0; t < NT; t++) {
            float al = SCALING * sal[b * NT + t];
            a0 += al * s0[t];
            a1 += al * s1[t];
        }
        *(__half2*)(g_agg + (long)b * WELEM + g0) = __floats2half2_rn(a0, a1);
    }
}

// ---------------------------------------------------------------------------
// Kernel C: fp16 mma.sync m16n8k16 with **fp16 accumulators**, flushed to
// fp32 master accumulators once per KC=128 chunk (bounds fp16 error walk).
// CTA: 256 threads (8 warps, 4m x 2n), M=256, N=112, warp tile 64x56.
// K=2304 in 18 chunks of 128; 2-stage cp.async, one barrier per chunk.
// ---------------------------------------------------------------------------
#define KC      128
#define NCHUNK  18
#define ASTRB   272                     // A row stride bytes (128 halves + 8 pad)
#define ABYTES  (256 * ASTRB)           // 69632
#define BSTRB   272                     // B ci stride bytes (2 rows x 128B + 16)
#define BBYTES  (KC * BSTRB)            // 34816
#define STBYTES (ABYTES + BBYTES)       // 104448
#define STAGES  2
#define CONV_SMEM (STAGES * STBYTES)    // 208896

__global__ __launch_bounds__(256, 1)
void conv_mma_kernel(float* __restrict__ out) {
    extern __shared__ uint32_t sm[];
    const uint32_t smb = smem_u32(sm);

    const int tid  = threadIdx.x;
    const int lane = tid & 31;
    const int wid  = tid >> 5;
    const int wm   = wid >> 1;      // 0..3: m offset wm*64
    const int wn   = wid & 1;       // 0..1: image row within 2-row tile
    const int q    = lane >> 2;
    const int t4   = lane & 3;

    const int b  = blockIdx.y;
    const int nt = blockIdx.x;      // 0..27
    const int y0 = nt * 2;

    const __half* agg_b = g_agg + (long)b * WELEM;

    const int gA = lane >> 3, rA = lane & 7;
    const uint32_t a_lane = (uint32_t)(((gA & 1) * 8 + rA) * ASTRB + (gA >> 1) * 16);
    const uint32_t b_lane = (uint32_t)((lane & 15) * BSTRB + wn * 128);

    auto issue = [&](int c, int buf) {
        uint32_t sa = smb + buf * STBYTES;
#pragma unroll
        for (int j = 0; j < 16; j++) {
            int idx = tid + j * 256;
            int m = idx >> 4, seg = idx & 15;
            cp16(sa + m * ASTRB + seg * 16,
                 agg_b + (long)m * KTOT + c * KC + seg * 8);
        }
        int tap = c >> 1;
        int ci0 = (c & 1) * 128;
        int kh = tap / 3, kw = tap % 3;
        const __half* gsrc = g_xpad
            + ((long)(kw * BATCH + b) * CIN + ci0) * PPLANE + (y0 + kh) * PWH;
        uint32_t bb = sa + ABYTES;
#pragma unroll
        for (int j = 0; j < 8; j++) {
            int idx = tid + j * 256;
            int rowid = idx >> 3, seg = idx & 7;
            int ci = rowid >> 1, yy = rowid & 1;
            cp16(bb + ci * BSTRB + yy * 128 + seg * 16,
                 gsrc + (long)ci * PPLANE + yy * PWH + seg * 8);
        }
        asm volatile("cp.async.commit_group;" ::: "memory");
    };

    issue(0, 0);

    float acc[4][7][4];
#pragma unroll
    for (int i = 0; i < 4; i++)
#pragma unroll
        for (int j = 0; j < 7; j++)
#pragma unroll
            for (int e = 0; e < 4; e++) acc[i][j][e] = 0.f;

    for (int c = 0; c < NCHUNK; c++) {
        asm volatile("cp.async.wait_group 0;" ::: "memory");
        __syncthreads();

        if (c + 1 < NCHUNK) issue(c + 1, (c + 1) & 1);

        const uint32_t stage = smb + (c & 1) * STBYTES;
        const uint32_t aw = stage + (wm * 64) * ASTRB + a_lane;
        const uint32_t bw = stage + ABYTES + b_lane;

        // fp16 chunk accumulators (zeroed each chunk)
        uint32_t hacc[4][7][2];
#pragma unroll
        for (int ms = 0; ms < 4; ms++)
#pragma unroll
            for (int ns = 0; ns < 7; ns++) { hacc[ms][ns][0] = 0u; hacc[ms][ns][1] = 0u; }

#pragma unroll
        for (int ks = 0; ks < 8; ks++) {
            const int kk = ks * 16;
            uint32_t bf[7][2];
#pragma unroll
            for (int ns = 0; ns < 7; ns++)
                ldsmBT(bf[ns], bw + kk * BSTRB + ns * 16);
#pragma unroll
            for (int ms = 0; ms < 4; ms++) {
                uint32_t af[4];
                ldsmA(af, aw + ms * (16 * ASTRB) + kk * 2);
#pragma unroll
                for (int ns = 0; ns < 7; ns++)
                    hmma16(hacc[ms][ns], af, bf[ns]);
            }
        }

        // flush fp16 chunk sums into fp32 master accumulators
#pragma unroll
        for (int ms = 0; ms < 4; ms++)
#pragma unroll
            for (int ns = 0; ns < 7; ns++) {
                float2 lo = __half22float2(*(__half2*)&hacc[ms][ns][0]);
                float2 hi = __half22float2(*(__half2*)&hacc[ms][ns][1]);
                acc[ms][ns][0] += lo.x;
                acc[ms][ns][1] += lo.y;
                acc[ms][ns][2] += hi.x;
                acc[ms][ns][3] += hi.y;
            }
    }

    // ---- epilogue ----
    {
        const int nbase = nt * 112 + wn * 56;
#pragma unroll
        for (int ms = 0; ms < 4; ms++) {
            int row0 = wm * 64 + ms * 16 + q;
#pragma unroll
            for (int ns = 0; ns < 7; ns++) {
                int np = nbase + ns * 8 + t4 * 2;
                *(float2*)(out + ((long)(b * COUT + row0)) * HW + np) =
                    make_float2(acc[ms][ns][0], acc[ms][ns][1]);
                *(float2*)(out + ((long)(b * COUT + row0 + 8)) * HW + np) =
                    make_float2(acc[ms][ns][2], acc[ms][ns][3]);
            }
        }
    }
}

// ---------------------------------------------------------------------------
extern "C" void kernel_launch(void* const* d_in, const int* in_sizes, int n_in,
                              void* d_out, int out_size) {
    const float* x      = (const float*)d_in[0];
    const float* alphas = (const float*)d_in[1];
    const float* conv_w = (const float*)d_in[2];
    const float* lora_A = (const float*)d_in[3];
    const float* lora_B = (const float*)d_in[4];
    float* out = (float*)d_out;

    pad_kernel<<<BATCH * CIN, 256>>>(x);

    dim3 gA(DIM / 128, DIM / 32, NT);
    synth_stack_kernel<<<gA, 256>>>(lora_A, lora_B);

    build_agg_kernel<<<WELEM / 512, 256>>>(alphas, conv_w);

    cudaFuncSetAttribute(conv_mma_kernel,
                         cudaFuncAttributeMaxDynamicSharedMemorySize, CONV_SMEM);
    dim3 gC(28, BATCH);
    conv_mma_kernel<<<gC, 256, CONV_SMEM>>>(out);
}

// round 11
// speedup vs baseline: 1.0560x; 1.0560x over previous
#include <cuda_runtime.h>
#include <cuda_fp16.h>
#include <cstdint>

// ---------------- problem constants ----------------
#define NT    8
#define RK    48
#define DIM   768
#define BATCH 32
#define CIN   256
#define COUT  256
#define HH    56
#define WW    56
#define HW    3136
#define KTOT  2304            // Cin*9, reordered as tap*256+ci
#define WELEM (COUT*KTOT)     // 589824
#define SCALING 2.0f
#define PWH   64              // padded row width in halves (128B rows)
#define PH    58
#define PPLANE (PH*PWH)       // 3712

// ---------------- scratch (device globals) ----------------
__device__ float  g_stack[NT * DIM * DIM];                 // [t][f], f = o*2304+ci*9+tap
__device__ __half g_agg[(long)BATCH * WELEM];              // [b][o][tap*256+ci], fp16
__device__ __half g_xpad[3L * BATCH * CIN * PPLANE];       // [kw][b][ci][58][64], fp16

__device__ __forceinline__ uint32_t smem_u32(const void* p) {
    uint32_t a;
    asm("{ .reg .u64 t; cvta.to.shared.u64 t, %1; cvt.u32.u64 %0, t; }" : "=r"(a) : "l"(p));
    return a;
}
__device__ __forceinline__ void cp16(uint32_t dst, const void* src) {
    asm volatile("cp.async.cg.shared.global [%0], [%1], 16;" :: "r"(dst), "l"(src));
}
__device__ __forceinline__ void ldsmA(uint32_t* r, uint32_t addr) {
    asm volatile("ldmatrix.sync.aligned.m8n8.x4.shared.b16 {%0,%1,%2,%3}, [%4];"
                 : "=r"(r[0]), "=r"(r[1]), "=r"(r[2]), "=r"(r[3]) : "r"(addr));
}
__device__ __forceinline__ void ldsmBT(uint32_t* r, uint32_t addr) {
    asm volatile("ldmatrix.sync.aligned.m8n8.x2.trans.shared.b16 {%0,%1}, [%2];"
                 : "=r"(r[0]), "=r"(r[1]) : "r"(addr));
}
__device__ __forceinline__ void hmma(float* d, const uint32_t* a, const uint32_t* b) {
    asm volatile(
        "mma.sync.aligned.m16n8k16.row.col.f32.f16.f16.f32 "
        "{%0,%1,%2,%3}, {%4,%5,%6,%7}, {%8,%9}, {%0,%1,%2,%3};"
        : "+f"(d[0]), "+f"(d[1]), "+f"(d[2]), "+f"(d[3])
        : "r"(a[0]), "r"(a[1]), "r"(a[2]), "r"(a[3]), "r"(b[0]), "r"(b[1]));
}

// ---------------------------------------------------------------------------
// Kernel P (R5 version — measured fastest): 3 kw-shifted zero-padded fp16
// copies of x, 16B stores. copy[kw][ci][y'][xx'] = x[ci][y'-1][xx'+kw-1]
// ---------------------------------------------------------------------------
__global__ void pad_kernel(const float* __restrict__ x) {
    int plane = blockIdx.x;                 // b*256+ci
    const float* src = x + (long)plane * HW;
#pragma unroll
    for (int kw = 0; kw < 3; kw++) {
        __half* dst = g_xpad + ((long)kw * BATCH * CIN + plane) * PPLANE;
        for (int i8 = threadIdx.x; i8 < PPLANE / 8; i8 += 256) {
            int y   = i8 >> 3;
            int xs0 = (i8 & 7) * 8;
            __half2 h[4];
#pragma unroll
            for (int p = 0; p < 4; p++) {
                float v0 = 0.f, v1 = 0.f;
                if (y >= 1 && y <= HH) {
                    const float* row = src + (y - 1) * WW;
                    int xc = xs0 + p * 2 + kw - 1;
                    if (xc >= 0 && xc < WW) v0 = row[xc];
                    if (xc + 1 >= 0 && xc + 1 < WW) v1 = row[xc + 1];
                }
                h[p] = __floats2half2_rn(v0, v1);
            }
            *(float4*)(dst + i8 * 8) = *(float4*)h;
        }
    }
}

// ---------------------------------------------------------------------------
// Kernel A (R5): stack[t] = lora_B[t] (768x48) @ lora_A[t] (48x768)
// ---------------------------------------------------------------------------
__global__ void synth_stack_kernel(const float* __restrict__ lora_A,
                                   const float* __restrict__ lora_B) {
    int t    = blockIdx.z;
    int row0 = blockIdx.y * 32;
    int col0 = blockIdx.x * 128;
    __shared__ float Bs[32][RK + 1];
    __shared__ float As[RK][128];
    int tid = threadIdx.x;

    for (int i = tid; i < 32 * RK; i += 256) {
        int r = i / RK, k = i % RK;
        Bs[r][k] = lora_B[((long)t * DIM + row0 + r) * RK + k];
    }
    for (int i = tid; i < RK * 32; i += 256) {
        int k = i / 32, c4 = i % 32;
        *(float4*)&As[k][c4 * 4] =
            *(const float4*)(lora_A + ((long)t * RK + k) * DIM + col0 + c4 * 4);
    }
    __syncthreads();

    int r  = tid >> 3;
    int c0 = (tid & 7) * 16;
    float acc[16];
#pragma unroll
    for (int j = 0; j < 16; j++) acc[j] = 0.f;
#pragma unroll
    for (int k = 0; k < RK; k++) {
        float bv = Bs[r][k];
#pragma unroll
        for (int j = 0; j < 16; j++) acc[j] += bv * As[k][c0 + j];
    }
    float* dst = &g_stack[((long)t * DIM + row0 + r) * DIM + col0 + c0];
#pragma unroll
    for (int j4 = 0; j4 < 4; j4++)
        *(float4*)(dst + j4 * 4) = make_float4(acc[j4*4], acc[j4*4+1], acc[j4*4+2], acc[j4*4+3]);
}

// ---------------------------------------------------------------------------
// Kernel B (R5 v2 — measured fastest): thread handles 2 consecutive reordered
// indices, half2 stores. g = o*2304 + tap*256 + ci, f = o*2304 + ci*9 + tap.
// ---------------------------------------------------------------------------
__global__ void build_agg_kernel(const float* __restrict__ alphas,
                                 const float* __restrict__ conv_w) {
    __shared__ float sal[BATCH * NT];
    int tid = threadIdx.x;
    sal[tid] = alphas[tid];
    __syncthreads();

    long g0 = ((long)blockIdx.x * 256 + tid) * 2;
    int o   = (int)(g0 / KTOT);
    int r2  = (int)(g0 % KTOT);
    int tap = r2 >> 8;
    int ci  = r2 & 255;
    long f0 = (long)o * KTOT + ci * 9 + tap;
    long f1 = f0 + 9;

    float s0[NT], s1[NT];
#pragma unroll
    for (int t = 0; t < NT; t++) {
        s0[t] = g_stack[(long)t * WELEM + f0];
        s1[t] = g_stack[(long)t * WELEM + f1];
    }
    float w0 = conv_w[f0], w1 = conv_w[f1];

#pragma unroll 4
    for (int b = 0; b < BATCH; b++) {
        float a0 = w0, a1 = w1;
#pragma unroll
        for (int t = 0; t < NT; t++) {
            float al = SCALING * sal[b * NT + t];
            a0 += al * s0[t];
            a1 += al * s1[t];
        }
        *(__half2*)(g_agg + (long)b * WELEM + g0) = __floats2half2_rn(a0, a1);
    }
}

// ---------------------------------------------------------------------------
// Kernel C (R6 — measured fastest conv, 343.9us): fp16 mma.sync m16n8k16.
// CTA: 256 threads (8 warps, 4m x 2n), M=128, N=112 (2 rows x 56 px),
// K=2304 in 36 chunks of 64. 3-stage cp.async pipeline, 2 CTAs/SM.
// ---------------------------------------------------------------------------
#define KC      64
#define NCHUNK  36
#define ASTRB   144                     // A row stride bytes (72 halves)
#define ABYTES  (128 * ASTRB)           // 18432
#define BSTRB   272                     // B ci stride bytes (2 rows x 128B + 16 pad)
#define BBYTES  (KC * BSTRB)            // 17408
#define STBYTES (ABYTES + BBYTES)       // 35840
#define STAGES  3
#define CONV_SMEM (STAGES * STBYTES)    // 107520

__global__ __launch_bounds__(256, 2)
void conv_mma_kernel(float* __restrict__ out) {
    extern __shared__ uint32_t sm[];
    const uint32_t smb = smem_u32(sm);

    const int tid  = threadIdx.x;
    const int lane = tid & 31;
    const int wid  = tid >> 5;
    const int wm   = wid >> 1;      // 0..3: m offset wm*32
    const int wn   = wid & 1;       // 0..1: image row within 2-row tile
    const int q    = lane >> 2;     // 0..7
    const int t4   = lane & 3;      // 0..3

    const int b  = blockIdx.z;
    const int mt = blockIdx.y;      // 0..1
    const int nt = blockIdx.x;      // 0..27
    const int y0 = nt * 2;

    const __half* agg_b = g_agg + (long)b * WELEM + (long)(mt * 128) * KTOT;

    const int gA = lane >> 3, rA = lane & 7;
    const uint32_t a_lane = (uint32_t)(((gA & 1) * 8 + rA) * ASTRB + (gA >> 1) * 16);
    const uint32_t b_lane = (uint32_t)((lane & 15) * BSTRB + wn * 128);

    auto issue = [&](int c, int buf) {
        uint32_t sa = smb + buf * STBYTES;
        // A: 128 rows x 128B = 1024 x 16B (4 per thread)
#pragma unroll
        for (int j = 0; j < 4; j++) {
            int idx = tid + j * 256;
            int m = idx >> 3, seg = idx & 7;
            cp16(sa + m * ASTRB + seg * 16,
                 agg_b + (long)m * KTOT + c * KC + seg * 8);
        }
        // B: 64 ci x 2 rows x 128B = 1024 x 16B
        int tap = c >> 2;
        int ci0 = (c & 3) * 64;
        int kh = tap / 3, kw = tap % 3;
        const __half* gsrc = g_xpad
            + ((long)(kw * BATCH + b) * CIN + ci0) * PPLANE + (y0 + kh) * PWH;
        uint32_t bb = sa + ABYTES;
#pragma unroll
        for (int j = 0; j < 4; j++) {
            int idx = tid + j * 256;
            int rowid = idx >> 3, seg = idx & 7;
            int ci = rowid >> 1, yy = rowid & 1;
            cp16(bb + ci * BSTRB + yy * 128 + seg * 16,
                 gsrc + (long)ci * PPLANE + yy * PWH + seg * 8);
        }
        asm volatile("cp.async.commit_group;" ::: "memory");
    };

    issue(0, 0);
    issue(1, 1);

    float acc[2][7][4];
#pragma unroll
    for (int i = 0; i < 2; i++)
#pragma unroll
        for (int j = 0; j < 7; j++)
#pragma unroll
            for (int e = 0; e < 4; e++) acc[i][j][e] = 0.f;

    for (int c = 0; c < NCHUNK; c++) {
        asm volatile("cp.async.wait_group 1;" ::: "memory");
        __syncthreads();

        const int buf = c % 3;
        if (c + 2 < NCHUNK) issue(c + 2, (c + 2) % 3);
        else asm volatile("cp.async.commit_group;" ::: "memory");

        const uint32_t stage = smb + buf * STBYTES;
        const uint32_t aw = stage + (wm * 32) * ASTRB + a_lane;
        const uint32_t bw = stage + ABYTES + b_lane;

#pragma unroll
        for (int ks = 0; ks < 4; ks++) {
            const int kk = ks * 16;
            uint32_t af[2][4];
#pragma unroll
            for (int ms = 0; ms < 2; ms++) {
                ldsmA(af[ms], aw + ms * (16 * ASTRB) + kk * 2);
            }
            uint32_t bf[7][2];
#pragma unroll
            for (int ns = 0; ns < 7; ns++) {
                ldsmBT(bf[ns], bw + kk * BSTRB + ns * 16);
            }
#pragma unroll
            for (int ms = 0; ms < 2; ms++)
#pragma unroll
                for (int ns = 0; ns < 7; ns++)
                    hmma(acc[ms][ns], af[ms], bf[ns]);
        }
    }

    // ---- epilogue ----
    {
        const int mbase = mt * 128 + wm * 32;
        const int nbase = nt * 112 + wn * 56;
#pragma unroll
        for (int ms = 0; ms < 2; ms++) {
            int row0 = mbase + ms * 16 + q;
#pragma unroll
            for (int ns = 0; ns < 7; ns++) {
                int np = nbase + ns * 8 + t4 * 2;
                *(float2*)(out + ((long)(b * COUT + row0)) * HW + np) =
                    make_float2(acc[ms][ns][0], acc[ms][ns][1]);
                *(float2*)(out + ((long)(b * COUT + row0 + 8)) * HW + np) =
                    make_float2(acc[ms][ns][2], acc[ms][ns][3]);
            }
        }
    }
}

// ---------------------------------------------------------------------------
extern "C" void kernel_launch(void* const* d_in, const int* in_sizes, int n_in,
                              void* d_out, int out_size) {
    const float* x      = (const float*)d_in[0];
    const float* alphas = (const float*)d_in[1];
    const float* conv_w = (const float*)d_in[2];
    const float* lora_A = (const float*)d_in[3];
    const float* lora_B = (const float*)d_in[4];
    float* out = (float*)d_out;

    pad_kernel<<<BATCH * CIN, 256>>>(x);

    dim3 gA(DIM / 128, DIM / 32, NT);
    synth_stack_kernel<<<gA, 256>>>(lora_A, lora_B);

    build_agg_kernel<<<WELEM / 512, 256>>>(alphas, conv_w);

    cudaFuncSetAttribute(conv_mma_kernel,
                         cudaFuncAttributeMaxDynamicSharedMemorySize, CONV_SMEM);
    dim3 gC(28, 2, BATCH);
    conv_mma_kernel<<<gC, 256, CONV_SMEM>>>(out);
}

// round 12
// speedup vs baseline: 1.0593x; 1.0031x over previous
#include <cuda_runtime.h>
#include <cuda_fp16.h>
#include <cstdint>

// ---------------- problem constants ----------------
#define NT    8
#define RK    48
#define DIM   768
#define BATCH 32
#define CIN   256
#define COUT  256
#define HH    56
#define WW    56
#define HW    3136
#define KTOT  2304            // Cin*9, reordered as tap*256+ci
#define WELEM (COUT*KTOT)     // 589824
#define SCALING 2.0f
#define PWH   64              // padded row width in halves (128B rows)
#define PH    58
#define PPLANE (PH*PWH)       // 3712

#define PAD_BLOCKS (BATCH * CIN)        // 8192
#define AGG_BLOCKS (WELEM / 512)        // 1152

// ---------------- scratch (device globals) ----------------
__device__ float  g_stack[NT * DIM * DIM];                 // [t][f], f = o*2304+ci*9+tap
__device__ __half g_agg[(long)BATCH * WELEM];              // [b][o][tap*256+ci], fp16
__device__ __half g_xpad[3L * BATCH * CIN * PPLANE];       // [kw][b][ci][58][64], fp16

__device__ __forceinline__ uint32_t smem_u32(const void* p) {
    uint32_t a;
    asm("{ .reg .u64 t; cvta.to.shared.u64 t, %1; cvt.u32.u64 %0, t; }" : "=r"(a) : "l"(p));
    return a;
}
__device__ __forceinline__ void cp16(uint32_t dst, const void* src) {
    asm volatile("cp.async.cg.shared.global [%0], [%1], 16;" :: "r"(dst), "l"(src));
}
__device__ __forceinline__ void ldsmA(uint32_t* r, uint32_t addr) {
    asm volatile("ldmatrix.sync.aligned.m8n8.x4.shared.b16 {%0,%1,%2,%3}, [%4];"
                 : "=r"(r[0]), "=r"(r[1]), "=r"(r[2]), "=r"(r[3]) : "r"(addr));
}
__device__ __forceinline__ void ldsmBT(uint32_t* r, uint32_t addr) {
    asm volatile("ldmatrix.sync.aligned.m8n8.x2.trans.shared.b16 {%0,%1}, [%2];"
                 : "=r"(r[0]), "=r"(r[1]) : "r"(addr));
}
__device__ __forceinline__ void hmma(float* d, const uint32_t* a, const uint32_t* b) {
    asm volatile(
        "mma.sync.aligned.m16n8k16.row.col.f32.f16.f16.f32 "
        "{%0,%1,%2,%3}, {%4,%5,%6,%7}, {%8,%9}, {%0,%1,%2,%3};"
        : "+f"(d[0]), "+f"(d[1]), "+f"(d[2]), "+f"(d[3])
        : "r"(a[0]), "r"(a[1]), "r"(a[2]), "r"(a[3]), "r"(b[0]), "r"(b[1]));
}

// ---------------------------------------------------------------------------
// Kernel A (R5): stack[t] = lora_B[t] (768x48) @ lora_A[t] (48x768)
// ---------------------------------------------------------------------------
__global__ void synth_stack_kernel(const float* __restrict__ lora_A,
                                   const float* __restrict__ lora_B) {
    int t    = blockIdx.z;
    int row0 = blockIdx.y * 32;
    int col0 = blockIdx.x * 128;
    __shared__ float Bs[32][RK + 1];
    __shared__ float As[RK][128];
    int tid = threadIdx.x;

    for (int i = tid; i < 32 * RK; i += 256) {
        int r = i / RK, k = i % RK;
        Bs[r][k] = lora_B[((long)t * DIM + row0 + r) * RK + k];
    }
    for (int i = tid; i < RK * 32; i += 256) {
        int k = i / 32, c4 = i % 32;
        *(float4*)&As[k][c4 * 4] =
            *(const float4*)(lora_A + ((long)t * RK + k) * DIM + col0 + c4 * 4);
    }
    __syncthreads();

    int r  = tid >> 3;
    int c0 = (tid & 7) * 16;
    float acc[16];
#pragma unroll
    for (int j = 0; j < 16; j++) acc[j] = 0.f;
#pragma unroll
    for (int k = 0; k < RK; k++) {
        float bv = Bs[r][k];
#pragma unroll
        for (int j = 0; j < 16; j++) acc[j] += bv * As[k][c0 + j];
    }
    float* dst = &g_stack[((long)t * DIM + row0 + r) * DIM + col0 + c0];
#pragma unroll
    for (int j4 = 0; j4 < 4; j4++)
        *(float4*)(dst + j4 * 4) = make_float4(acc[j4*4], acc[j4*4+1], acc[j4*4+2], acc[j4*4+3]);
}

// ---------------------------------------------------------------------------
// Fused prologue: blocks [0, PAD_BLOCKS) = pad (R5 version, bit-identical);
// blocks [PAD_BLOCKS, PAD_BLOCKS+AGG_BLOCKS) = agg (R5 v2, bit-identical).
// The two independent workloads overlap: pad streams DRAM while agg's
// strided stack gathers are latency-bound.
// ---------------------------------------------------------------------------
__global__ void fused_pad_agg_kernel(const float* __restrict__ x,
                                     const float* __restrict__ alphas,
                                     const float* __restrict__ conv_w) {
    if (blockIdx.x < PAD_BLOCKS) {
        // ------------------ pad ------------------
        int plane = blockIdx.x;                 // b*256+ci
        const float* src = x + (long)plane * HW;
#pragma unroll
        for (int kw = 0; kw < 3; kw++) {
            __half* dst = g_xpad + ((long)kw * BATCH * CIN + plane) * PPLANE;
            for (int i8 = threadIdx.x; i8 < PPLANE / 8; i8 += 256) {
                int y   = i8 >> 3;
                int xs0 = (i8 & 7) * 8;
                __half2 h[4];
#pragma unroll
                for (int p = 0; p < 4; p++) {
                    float v0 = 0.f, v1 = 0.f;
                    if (y >= 1 && y <= HH) {
                        const float* row = src + (y - 1) * WW;
                        int xc = xs0 + p * 2 + kw - 1;
                        if (xc >= 0 && xc < WW) v0 = row[xc];
                        if (xc + 1 >= 0 && xc + 1 < WW) v1 = row[xc + 1];
                    }
                    h[p] = __floats2half2_rn(v0, v1);
                }
                *(float4*)(dst + i8 * 8) = *(float4*)h;
            }
        }
    } else {
        // ------------------ agg ------------------
        __shared__ float sal[BATCH * NT];
        int tid = threadIdx.x;
        sal[tid] = alphas[tid];
        __syncthreads();

        long g0 = ((long)(blockIdx.x - PAD_BLOCKS) * 256 + tid) * 2;
        int o   = (int)(g0 / KTOT);
        int r2  = (int)(g0 % KTOT);
        int tap = r2 >> 8;
        int ci  = r2 & 255;
        long f0 = (long)o * KTOT + ci * 9 + tap;
        long f1 = f0 + 9;

        float s0[NT], s1[NT];
#pragma unroll
        for (int t = 0; t < NT; t++) {
            s0[t] = g_stack[(long)t * WELEM + f0];
            s1[t] = g_stack[(long)t * WELEM + f1];
        }
        float w0 = conv_w[f0], w1 = conv_w[f1];

#pragma unroll 4
        for (int b = 0; b < BATCH; b++) {
            float a0 = w0, a1 = w1;
#pragma unroll
            for (int t = 0; t < NT; t++) {
                float al = SCALING * sal[b * NT + t];
                a0 += al * s0[t];
                a1 += al * s1[t];
            }
            *(__half2*)(g_agg + (long)b * WELEM + g0) = __floats2half2_rn(a0, a1);
        }
    }
}

// ---------------------------------------------------------------------------
// Kernel C (R6 — measured fastest conv, 343.9us): fp16 mma.sync m16n8k16.
// CTA: 256 threads (8 warps, 4m x 2n), M=128, N=112 (2 rows x 56 px),
// K=2304 in 36 chunks of 64. 3-stage cp.async pipeline, 2 CTAs/SM.
// ---------------------------------------------------------------------------
#define KC      64
#define NCHUNK  36
#define ASTRB   144                     // A row stride bytes (72 halves)
#define ABYTES  (128 * ASTRB)           // 18432
#define BSTRB   272                     // B ci stride bytes (2 rows x 128B + 16 pad)
#define BBYTES  (KC * BSTRB)            // 17408
#define STBYTES (ABYTES + BBYTES)       // 35840
#define STAGES  3
#define CONV_SMEM (STAGES * STBYTES)    // 107520

__global__ __launch_bounds__(256, 2)
void conv_mma_kernel(float* __restrict__ out) {
    extern __shared__ uint32_t sm[];
    const uint32_t smb = smem_u32(sm);

    const int tid  = threadIdx.x;
    const int lane = tid & 31;
    const int wid  = tid >> 5;
    const int wm   = wid >> 1;      // 0..3: m offset wm*32
    const int wn   = wid & 1;       // 0..1: image row within 2-row tile
    const int q    = lane >> 2;     // 0..7
    const int t4   = lane & 3;      // 0..3

    const int b  = blockIdx.z;
    const int mt = blockIdx.y;      // 0..1
    const int nt = blockIdx.x;      // 0..27
    const int y0 = nt * 2;

    const __half* agg_b = g_agg + (long)b * WELEM + (long)(mt * 128) * KTOT;

    const int gA = lane >> 3, rA = lane & 7;
    const uint32_t a_lane = (uint32_t)(((gA & 1) * 8 + rA) * ASTRB + (gA >> 1) * 16);
    const uint32_t b_lane = (uint32_t)((lane & 15) * BSTRB + wn * 128);

    auto issue = [&](int c, int buf) {
        uint32_t sa = smb + buf * STBYTES;
        // A: 128 rows x 128B = 1024 x 16B (4 per thread)
#pragma unroll
        for (int j = 0; j < 4; j++) {
            int idx = tid + j * 256;
            int m = idx >> 3, seg = idx & 7;
            cp16(sa + m * ASTRB + seg * 16,
                 agg_b + (long)m * KTOT + c * KC + seg * 8);
        }
        // B: 64 ci x 2 rows x 128B = 1024 x 16B
        int tap = c >> 2;
        int ci0 = (c & 3) * 64;
        int kh = tap / 3, kw = tap % 3;
        const __half* gsrc = g_xpad
            + ((long)(kw * BATCH + b) * CIN + ci0) * PPLANE + (y0 + kh) * PWH;
        uint32_t bb = sa + ABYTES;
#pragma unroll
        for (int j = 0; j < 4; j++) {
            int idx = tid + j * 256;
            int rowid = idx >> 3, seg = idx & 7;
            int ci = rowid >> 1, yy = rowid & 1;
            cp16(bb + ci * BSTRB + yy * 128 + seg * 16,
                 gsrc + (long)ci * PPLANE + yy * PWH + seg * 8);
        }
        asm volatile("cp.async.commit_group;" ::: "memory");
    };

    issue(0, 0);
    issue(1, 1);

    float acc[2][7][4];
#pragma unroll
    for (int i = 0; i < 2; i++)
#pragma unroll
        for (int j = 0; j < 7; j++)
#pragma unroll
            for (int e = 0; e < 4; e++) acc[i][j][e] = 0.f;

    for (int c = 0; c < NCHUNK; c++) {
        asm volatile("cp.async.wait_group 1;" ::: "memory");
        __syncthreads();

        const int buf = c % 3;
        if (c + 2 < NCHUNK) issue(c + 2, (c + 2) % 3);
        else asm volatile("cp.async.commit_group;" ::: "memory");

        const uint32_t stage = smb + buf * STBYTES;
        const uint32_t aw = stage + (wm * 32) * ASTRB + a_lane;
        const uint32_t bw = stage + ABYTES + b_lane;

#pragma unroll
        for (int ks = 0; ks < 4; ks++) {
            const int kk = ks * 16;
            uint32_t af[2][4];
#pragma unroll
            for (int ms = 0; ms < 2; ms++) {
                ldsmA(af[ms], aw + ms * (16 * ASTRB) + kk * 2);
            }
            uint32_t bf[7][2];
#pragma unroll
            for (int ns = 0; ns < 7; ns++) {
                ldsmBT(bf[ns], bw + kk * BSTRB + ns * 16);
            }
#pragma unroll
            for (int ms = 0; ms < 2; ms++)
#pragma unroll
                for (int ns = 0; ns < 7; ns++)
                    hmma(acc[ms][ns], af[ms], bf[ns]);
        }
    }

    // ---- epilogue ----
    {
        const int mbase = mt * 128 + wm * 32;
        const int nbase = nt * 112 + wn * 56;
#pragma unroll
        for (int ms = 0; ms < 2; ms++) {
            int row0 = mbase + ms * 16 + q;
#pragma unroll
            for (int ns = 0; ns < 7; ns++) {
                int np = nbase + ns * 8 + t4 * 2;
                *(float2*)(out + ((long)(b * COUT + row0)) * HW + np) =
                    make_float2(acc[ms][ns][0], acc[ms][ns][1]);
                *(float2*)(out + ((long)(b * COUT + row0 + 8)) * HW + np) =
                    make_float2(acc[ms][ns][2], acc[ms][ns][3]);
            }
        }
    }
}

// ---------------------------------------------------------------------------
extern "C" void kernel_launch(void* const* d_in, const int* in_sizes, int n_in,
                              void* d_out, int out_size) {
    const float* x      = (const float*)d_in[0];
    const float* alphas = (const float*)d_in[1];
    const float* conv_w = (const float*)d_in[2];
    const float* lora_A = (const float*)d_in[3];
    const float* lora_B = (const float*)d_in[4];
    float* out = (float*)d_out;

    // 1) synth (agg's only dependency)
    dim3 gA(DIM / 128, DIM / 32, NT);
    synth_stack_kernel<<<gA, 256>>>(lora_A, lora_B);

    // 2) pad + agg fused into one launch (independent workloads overlap)
    fused_pad_agg_kernel<<<PAD_BLOCKS + AGG_BLOCKS, 256>>>(x, alphas, conv_w);

    // 3) conv
    cudaFuncSetAttribute(conv_mma_kernel,
                         cudaFuncAttributeMaxDynamicSharedMemorySize, CONV_SMEM);
    dim3 gC(28, 2, BATCH);
    conv_mma_kernel<<<gC, 256, CONV_SMEM>>>(out);
}

// round 13
// speedup vs baseline: 1.2608x; 1.1902x over previous
#include <cuda_runtime.h>
#include <cuda_fp16.h>
#include <cstdint>

// ---------------- problem constants ----------------
#define NT    8
#define RK    48
#define DIM   768
#define BATCH 32
#define CIN   256
#define COUT  256
#define HH    56
#define WW    56
#define HW    3136
#define KTOT  2304            // Cin*9, reordered as tap*256+ci
#define WELEM (COUT*KTOT)     // 589824
#define SCALING 2.0f
#define PWH   64              // padded row width in halves (128B rows)
#define PH    58
#define PPLANE (PH*PWH)       // 3712

#define PAD_BLOCKS (BATCH * CIN)        // 8192
#define AGG_BLOCKS (WELEM / 512)        // 1152

// ---------------- scratch (device globals) ----------------
__device__ float  g_stack[NT * DIM * DIM];                 // [t][f], f = o*2304+ci*9+tap
__device__ __half g_agg[(long)BATCH * WELEM];              // [b][o][tap*256+ci], fp16
__device__ __half g_xpad[3L * BATCH * CIN * PPLANE];       // [kw][b][ci][58][64], fp16

__device__ __forceinline__ uint32_t smem_u32(const void* p) {
    uint32_t a;
    asm("{ .reg .u64 t; cvta.to.shared.u64 t, %1; cvt.u32.u64 %0, t; }" : "=r"(a) : "l"(p));
    return a;
}
__device__ __forceinline__ void cp16(uint32_t dst, const void* src) {
    asm volatile("cp.async.cg.shared.global [%0], [%1], 16;" :: "r"(dst), "l"(src));
}
__device__ __forceinline__ void ldsmA(uint32_t* r, uint32_t addr) {
    asm volatile("ldmatrix.sync.aligned.m8n8.x4.shared.b16 {%0,%1,%2,%3}, [%4];"
                 : "=r"(r[0]), "=r"(r[1]), "=r"(r[2]), "=r"(r[3]) : "r"(addr));
}
__device__ __forceinline__ void ldsmBT(uint32_t* r, uint32_t addr) {
    asm volatile("ldmatrix.sync.aligned.m8n8.x2.trans.shared.b16 {%0,%1}, [%2];"
                 : "=r"(r[0]), "=r"(r[1]) : "r"(addr));
}
__device__ __forceinline__ void hmma(float* d, const uint32_t* a, const uint32_t* b) {
    asm volatile(
        "mma.sync.aligned.m16n8k16.row.col.f32.f16.f16.f32 "
        "{%0,%1,%2,%3}, {%4,%5,%6,%7}, {%8,%9}, {%0,%1,%2,%3};"
        : "+f"(d[0]), "+f"(d[1]), "+f"(d[2]), "+f"(d[3])
        : "r"(a[0]), "r"(a[1]), "r"(a[2]), "r"(a[3]), "r"(b[0]), "r"(b[1]));
}

// ---------------------------------------------------------------------------
// Kernel A v3: stack[t] = lora_B[t] (768x48) @ lora_A[t] (48x768).
// 128x128 block tile, 4x16 thread tile, k-contiguous smem (stride 52 ->
// conflict-free LDS.128), float4 dot over k. grid (6,6,8), 256 threads.
// ---------------------------------------------------------------------------
#define SSTR 52

__global__ void synth_stack_kernel(const float* __restrict__ lora_A,
                                   const float* __restrict__ lora_B) {
    int t    = blockIdx.z;
    int row0 = blockIdx.y * 128;
    int col0 = blockIdx.x * 128;
    __shared__ float BsT[128][SSTR];
    __shared__ float AsT[128][SSTR];
    int tid = threadIdx.x;

    // stage B rows (k-contiguous in global AND smem: conflict-free)
    for (int i = tid; i < 128 * RK; i += 256) {
        int r = i / RK, k = i - r * RK;
        BsT[r][k] = lora_B[((long)t * DIM + row0 + r) * RK + k];
    }
    // stage A transposed (coalesced global read; 4-way STS conflict accepted)
    for (int i = tid; i < RK * 128; i += 256) {
        int k = i >> 7, c = i & 127;
        AsT[c][k] = lora_A[((long)t * RK + k) * DIM + col0 + c];
    }
    __syncthreads();

    const int tr = tid >> 3;    // 0..31 -> rows tr + 32m
    const int cb = tid & 7;     // cols cb + 8j

    float acc[4][16];
#pragma unroll
    for (int m = 0; m < 4; m++)
#pragma unroll
        for (int j = 0; j < 16; j++) acc[m][j] = 0.f;

#pragma unroll
    for (int k4 = 0; k4 < RK / 4; k4++) {
        float4 b4[4];
#pragma unroll
        for (int m = 0; m < 4; m++)
            b4[m] = *(const float4*)&BsT[tr + 32 * m][k4 * 4];
#pragma unroll
        for (int j = 0; j < 16; j++) {
            float4 a4 = *(const float4*)&AsT[cb + 8 * j][k4 * 4];
#pragma unroll
            for (int m = 0; m < 4; m++)
                acc[m][j] += b4[m].x * a4.x + b4[m].y * a4.y
                           + b4[m].z * a4.z + b4[m].w * a4.w;
        }
    }

#pragma unroll
    for (int m = 0; m < 4; m++) {
        float* dst = &g_stack[((long)t * DIM + row0 + tr + 32 * m) * DIM + col0];
#pragma unroll
        for (int j = 0; j < 16; j++)
            dst[cb + 8 * j] = acc[m][j];
    }
}

// ---------------------------------------------------------------------------
// Fused prologue: blocks [0, PAD_BLOCKS) = pad (R5, bit-identical);
// blocks [PAD_BLOCKS, +AGG_BLOCKS) = agg (R5 v2, bit-identical).
// ---------------------------------------------------------------------------
__global__ void fused_pad_agg_kernel(const float* __restrict__ x,
                                     const float* __restrict__ alphas,
                                     const float* __restrict__ conv_w) {
    if (blockIdx.x < PAD_BLOCKS) {
        // ------------------ pad ------------------
        int plane = blockIdx.x;                 // b*256+ci
        const float* src = x + (long)plane * HW;
#pragma unroll
        for (int kw = 0; kw < 3; kw++) {
            __half* dst = g_xpad + ((long)kw * BATCH * CIN + plane) * PPLANE;
            for (int i8 = threadIdx.x; i8 < PPLANE / 8; i8 += 256) {
                int y   = i8 >> 3;
                int xs0 = (i8 & 7) * 8;
                __half2 h[4];
#pragma unroll
                for (int p = 0; p < 4; p++) {
                    float v0 = 0.f, v1 = 0.f;
                    if (y >= 1 && y <= HH) {
                        const float* row = src + (y - 1) * WW;
                        int xc = xs0 + p * 2 + kw - 1;
                        if (xc >= 0 && xc < WW) v0 = row[xc];
                        if (xc + 1 >= 0 && xc + 1 < WW) v1 = row[xc + 1];
                    }
                    h[p] = __floats2half2_rn(v0, v1);
                }
                *(float4*)(dst + i8 * 8) = *(float4*)h;
            }
        }
    } else {
        // ------------------ agg ------------------
        __shared__ float sal[BATCH * NT];
        int tid = threadIdx.x;
        sal[tid] = alphas[tid];
        __syncthreads();

        long g0 = ((long)(blockIdx.x - PAD_BLOCKS) * 256 + tid) * 2;
        int o   = (int)(g0 / KTOT);
        int r2  = (int)(g0 % KTOT);
        int tap = r2 >> 8;
        int ci  = r2 & 255;
        long f0 = (long)o * KTOT + ci * 9 + tap;
        long f1 = f0 + 9;

        float s0[NT], s1[NT];
#pragma unroll
        for (int t = 0; t < NT; t++) {
            s0[t] = g_stack[(long)t * WELEM + f0];
            s1[t] = g_stack[(long)t * WELEM + f1];
        }
        float w0 = conv_w[f0], w1 = conv_w[f1];

#pragma unroll 4
        for (int b = 0; b < BATCH; b++) {
            float a0 = w0, a1 = w1;
#pragma unroll
            for (int t = 0; t < NT; t++) {
                float al = SCALING * sal[b * NT + t];
                a0 += al * s0[t];
                a1 += al * s1[t];
            }
            *(__half2*)(g_agg + (long)b * WELEM + g0) = __floats2half2_rn(a0, a1);
        }
    }
}

// ---------------------------------------------------------------------------
// Kernel C (R6 — measured fastest conv, 343.9us): fp16 mma.sync m16n8k16.
// CTA: 256 threads (8 warps, 4m x 2n), M=128, N=112 (2 rows x 56 px),
// K=2304 in 36 chunks of 64. 3-stage cp.async pipeline, 2 CTAs/SM.
// ---------------------------------------------------------------------------
#define KC      64
#define NCHUNK  36
#define ASTRB   144                     // A row stride bytes (72 halves)
#define ABYTES  (128 * ASTRB)           // 18432
#define BSTRB   272                     // B ci stride bytes (2 rows x 128B + 16 pad)
#define BBYTES  (KC * BSTRB)            // 17408
#define STBYTES (ABYTES + BBYTES)       // 35840
#define STAGES  3
#define CONV_SMEM (STAGES * STBYTES)    // 107520

__global__ __launch_bounds__(256, 2)
void conv_mma_kernel(float* __restrict__ out) {
    extern __shared__ uint32_t sm[];
    const uint32_t smb = smem_u32(sm);

    const int tid  = threadIdx.x;
    const int lane = tid & 31;
    const int wid  = tid >> 5;
    const int wm   = wid >> 1;      // 0..3: m offset wm*32
    const int wn   = wid & 1;       // 0..1: image row within 2-row tile
    const int q    = lane >> 2;     // 0..7
    const int t4   = lane & 3;      // 0..3

    const int b  = blockIdx.z;
    const int mt = blockIdx.y;      // 0..1
    const int nt = blockIdx.x;      // 0..27
    const int y0 = nt * 2;

    const __half* agg_b = g_agg + (long)b * WELEM + (long)(mt * 128) * KTOT;

    const int gA = lane >> 3, rA = lane & 7;
    const uint32_t a_lane = (uint32_t)(((gA & 1) * 8 + rA) * ASTRB + (gA >> 1) * 16);
    const uint32_t b_lane = (uint32_t)((lane & 15) * BSTRB + wn * 128);

    auto issue = [&](int c, int buf) {
        uint32_t sa = smb + buf * STBYTES;
        // A: 128 rows x 128B = 1024 x 16B (4 per thread)
#pragma unroll
        for (int j = 0; j < 4; j++) {
            int idx = tid + j * 256;
            int m = idx >> 3, seg = idx & 7;
            cp16(sa + m * ASTRB + seg * 16,
                 agg_b + (long)m * KTOT + c * KC + seg * 8);
        }
        // B: 64 ci x 2 rows x 128B = 1024 x 16B
        int tap = c >> 2;
        int ci0 = (c & 3) * 64;
        int kh = tap / 3, kw = tap % 3;
        const __half* gsrc = g_xpad
            + ((long)(kw * BATCH + b) * CIN + ci0) * PPLANE + (y0 + kh) * PWH;
        uint32_t bb = sa + ABYTES;
#pragma unroll
        for (int j = 0; j < 4; j++) {
            int idx = tid + j * 256;
            int rowid = idx >> 3, seg = idx & 7;
            int ci = rowid >> 1, yy = rowid & 1;
            cp16(bb + ci * BSTRB + yy * 128 + seg * 16,
                 gsrc + (long)ci * PPLANE + yy * PWH + seg * 8);
        }
        asm volatile("cp.async.commit_group;" ::: "memory");
    };

    issue(0, 0);
    issue(1, 1);

    float acc[2][7][4];
#pragma unroll
    for (int i = 0; i < 2; i++)
#pragma unroll
        for (int j = 0; j < 7; j++)
#pragma unroll
            for (int e = 0; e < 4; e++) acc[i][j][e] = 0.f;

    for (int c = 0; c < NCHUNK; c++) {
        asm volatile("cp.async.wait_group 1;" ::: "memory");
        __syncthreads();

        const int buf = c % 3;
        if (c + 2 < NCHUNK) issue(c + 2, (c + 2) % 3);
        else asm volatile("cp.async.commit_group;" ::: "memory");

        const uint32_t stage = smb + buf * STBYTES;
        const uint32_t aw = stage + (wm * 32) * ASTRB + a_lane;
        const uint32_t bw = stage + ABYTES + b_lane;

#pragma unroll
        for (int ks = 0; ks < 4; ks++) {
            const int kk = ks * 16;
            uint32_t af[2][4];
#pragma unroll
            for (int ms = 0; ms < 2; ms++) {
                ldsmA(af[ms], aw + ms * (16 * ASTRB) + kk * 2);
            }
            uint32_t bf[7][2];
#pragma unroll
            for (int ns = 0; ns < 7; ns++) {
                ldsmBT(bf[ns], bw + kk * BSTRB + ns * 16);
            }
#pragma unroll
            for (int ms = 0; ms < 2; ms++)
#pragma unroll
                for (int ns = 0; ns < 7; ns++)
                    hmma(acc[ms][ns], af[ms], bf[ns]);
        }
    }

    // ---- epilogue ----
    {
        const int mbase = mt * 128 + wm * 32;
        const int nbase = nt * 112 + wn * 56;
#pragma unroll
        for (int ms = 0; ms < 2; ms++) {
            int row0 = mbase + ms * 16 + q;
#pragma unroll
            for (int ns = 0; ns < 7; ns++) {
                int np = nbase + ns * 8 + t4 * 2;
                *(float2*)(out + ((long)(b * COUT + row0)) * HW + np) =
                    make_float2(acc[ms][ns][0], acc[ms][ns][1]);
                *(float2*)(out + ((long)(b * COUT + row0 + 8)) * HW + np) =
                    make_float2(acc[ms][ns][2], acc[ms][ns][3]);
            }
        }
    }
}

// ---------------------------------------------------------------------------
extern "C" void kernel_launch(void* const* d_in, const int* in_sizes, int n_in,
                              void* d_out, int out_size) {
    const float* x      = (const float*)d_in[0];
    const float* alphas = (const float*)d_in[1];
    const float* conv_w = (const float*)d_in[2];
    const float* lora_A = (const float*)d_in[3];
    const float* lora_B = (const float*)d_in[4];
    float* out = (float*)d_out;

    // 1) synth (agg's only dependency) — v3, conflict-free
    dim3 gA(DIM / 128, DIM / 128, NT);
    synth_stack_kernel<<<gA, 256>>>(lora_A, lora_B);

    // 2) pad + agg fused (independent workloads overlap)
    fused_pad_agg_kernel<<<PAD_BLOCKS + AGG_BLOCKS, 256>>>(x, alphas, conv_w);

    // 3) conv
    cudaFuncSetAttribute(conv_mma_kernel,
                         cudaFuncAttributeMaxDynamicSharedMemorySize, CONV_SMEM);
    dim3 gC(28, 2, BATCH);
    conv_mma_kernel<<<gC, 256, CONV_SMEM>>>(out);
}